// round 8
// baseline (speedup 1.0000x reference)
#include <cuda_runtime.h>

// VectorNormSelection, round 8: warp-per-row, zero smem, DOUBLE-packed keys.
// Key = (double)( ((u64)norm_bits << 6) | (63 - idx) ).
//   - value < 2^38, integer -> exact in double (53-bit mantissa)
//   - norms >= 0 and finite -> all keys are positive finite doubles, and
//     double ordering == u64 integer ordering == (value desc, index asc)
//     EXACT jax.lax.top_k tie semantics.
//   - compare-exchange: DSETP (FP64 pipe, otherwise idle) + 2 SELP, instead
//     of 2x ISETP.EX + 2x SELP all on the saturated ALU pipe (R7: alu=89.5%).
// Network identical to R7 (validated): bitonic sort-16 of four 8-lane groups
// in parallel, then two bitonic-halving tree merges; top-16 sorted in lanes
// 0-7 (2 keys/lane). Gather from L1-hot row, coalesced stores.

#define WPB 8          // warps per block
#define RPW 4          // rows per warp

typedef unsigned long long u64;

__device__ __forceinline__ double cexg(double e, double p, bool takeMax) {
    return ((p > e) == takeMax) ? p : e;
}

// shuffle stage, partner lane = lane ^ JH, same slot; takeMax precomputed
template <int JH>
__device__ __forceinline__ void stage_x(double& e0, double& e1, bool takeMax) {
    double p0 = __shfl_xor_sync(0xffffffffu, e0, JH);
    double p1 = __shfl_xor_sync(0xffffffffu, e1, JH);
    e0 = cexg(e0, p0, takeMax);
    e1 = cexg(e1, p1, takeMax);
}

// element distance 1: both elements in-lane
__device__ __forceinline__ void stage_l(double& e0, double& e1, bool descR) {
    bool gt = e0 > e1;
    double hi = gt ? e0 : e1;
    double lo = gt ? e1 : e0;
    e0 = descR ? hi : lo;
    e1 = descR ? lo : hi;
}

__global__ void __launch_bounds__(WPB * 32)
vecnorm_topk_kernel(const float* __restrict__ x, float* __restrict__ out, int nrows)
{
    const int lane = threadIdx.x & 31;
    const int wg   = blockIdx.x * WPB + (threadIdx.x >> 5);
    const int rowBase = wg * RPW;

    // per-lane output routing constants
    const int f2 = 32 + lane;
    const int j1 = lane / 3, c1 = lane - 3 * j1;   // out float [lane]  <- rank j1 comp c1
    const int j2 = f2 / 3,   c2 = f2 - 3 * j2;     // out float [32+l]  <- rank j2 comp c2

    // hoisted direction predicates (row-independent)
    const bool d2 = ((lane & 1) == 0);
    const bool d4 = ((lane & 2) == 0);
    const bool d8 = ((lane & 4) == 0);
    const bool x1_d4 = (((lane & 1) == 0) == d4);
    const bool x2_d8 = (((lane & 2) == 0) == d8);
    const bool x1_d8 = (((lane & 1) == 0) == d8);
    const bool x4_T  = ((lane & 4) == 0);
    const bool x2_T  = ((lane & 2) == 0);
    const bool x1_T  = ((lane & 1) == 0);

#pragma unroll 1
    for (int i = 0; i < RPW; i++) {
        int row = rowBase + i;
        if (row >= nrows) break;

        // ---- load 6 floats (vectors 2*lane, 2*lane+1), coalesced ----
        const float* xr = x + (size_t)row * 192;
        const float2* xr2 = reinterpret_cast<const float2*>(xr);
        float2 a = xr2[3 * lane + 0];
        float2 b = xr2[3 * lane + 1];
        float2 c = xr2[3 * lane + 2];
        float n0 = fmaf(a.x, a.x, fmaf(a.y, a.y, b.x * b.x));
        float n1 = fmaf(b.y, b.y, fmaf(c.x, c.x, c.y * c.y));

        // ---- exact double-packed keys ----
        u64 k0 = ((u64)__float_as_uint(n0) << 6) | (u64)(63 - 2 * lane);
        u64 k1 = ((u64)__float_as_uint(n1) << 6) | (u64)(62 - 2 * lane);
        double e0 = __ull2double_rn(k0);   // exact: k < 2^38
        double e1 = __ull2double_rn(k1);

        // ---- bitonic sort-16 (desc) within each 8-lane group, 4 in parallel ----
        stage_l(e0, e1, d2);               // k=2  j=1
        stage_x<1>(e0, e1, x1_d4);         // k=4  j=2
        stage_l(e0, e1, d4);               //      j=1
        stage_x<2>(e0, e1, x2_d8);         // k=8  j=4
        stage_x<1>(e0, e1, x1_d8);         //      j=2
        stage_l(e0, e1, d8);               //      j=1
        stage_x<4>(e0, e1, x4_T);          // k=16 j=8 (final run: desc)
        stage_x<2>(e0, e1, x2_T);          //      j=4
        stage_x<1>(e0, e1, x1_T);          //      j=2
        stage_l(e0, e1, true);             //      j=1

        // ---- merge A: (g0,g1)->lanes0-7, (g2,g3)->lanes16-23 (parallel) ----
        {   // bitonic halving: partner element 15-i of sibling group = lane^15, slot flip
            double p0 = __shfl_xor_sync(0xffffffffu, e0, 15);
            double p1 = __shfl_xor_sync(0xffffffffu, e1, 15);
            e0 = (p1 > e0) ? p1 : e0;
            e1 = (p0 > e1) ? p0 : e1;
        }
        stage_x<4>(e0, e1, x4_T);          // clean j=8
        stage_x<2>(e0, e1, x2_T);          //       j=4
        stage_x<1>(e0, e1, x1_T);          //       j=2
        stage_l(e0, e1, true);             //       j=1

        // ---- merge B: lanes0-7 vs lanes16-23 -> top-16 in lanes 0-7 ----
        {   // partner lane = l ^ 23 (for l<8), slot flip
            double p0 = __shfl_xor_sync(0xffffffffu, e0, 23);
            double p1 = __shfl_xor_sync(0xffffffffu, e1, 23);
            e0 = (p1 > e0) ? p1 : e0;
            e1 = (p0 > e1) ? p0 : e1;
        }
        stage_x<4>(e0, e1, x4_T);
        stage_x<2>(e0, e1, x2_T);
        stage_x<1>(e0, e1, x1_T);
        stage_l(e0, e1, true);

        // ---- extract indices, broadcast, gather (L1-hot), coalesced store ----
        unsigned r0 = (unsigned)(u64)__double2ll_rn(e0);   // exact integer
        unsigned r1 = (unsigned)(u64)__double2ll_rn(e1);
        unsigned idx0 = 63u - (r0 & 63u);
        unsigned idx1 = 63u - (r1 & 63u);
        unsigned pk = idx0 | (idx1 << 8);                  // rank 2l | rank 2l+1

        unsigned pkA = __shfl_sync(0xffffffffu, pk, j1 >> 1);
        unsigned iA  = (j1 & 1) ? ((pkA >> 8) & 0xffu) : (pkA & 0xffu);
        unsigned pkB = __shfl_sync(0xffffffffu, pk, j2 >> 1);
        unsigned iB  = (j2 & 1) ? ((pkB >> 8) & 0xffu) : (pkB & 0xffu);

        float* outr = out + (size_t)row * 48;
        outr[lane] = xr[(int)iA * 3 + c1];
        if (lane < 16)
            outr[32 + lane] = xr[(int)iB * 3 + c2];
    }
}

extern "C" void kernel_launch(void* const* d_in, const int* in_sizes, int n_in,
                              void* d_out, int out_size)
{
    const float* x   = (const float*)d_in[0];
    float*       out = (float*)d_out;
    int nrows = in_sizes[0] / 192;
    int rowsPerBlock = WPB * RPW;
    int grid = (nrows + rowsPerBlock - 1) / rowsPerBlock;
    vecnorm_topk_kernel<<<grid, WPB * 32>>>(x, out, nrows);
}

// round 9
// speedup vs baseline: 4.3111x; 4.3111x over previous
#include <cuda_runtime.h>

// VectorNormSelection, round 9: warp-per-row, zero smem, SPLIT exact keys.
// Key = (float h = norm, u32 l = 63 - idx); compare:
//     g = (ph > h) || (ph == h && pl > l)
// For non-negative finite floats, float order == bit order, so this is
// bit-exact identical to R7's u64 (norm_bits<<32 | 63-idx) ordering --
// EXACT jax.lax.top_k (value desc, index asc) semantics. The float compares
// (FSETP) and float selects (FSEL) issue on the FP32/FMA side, offloading
// the saturated ALU pipe (R7: alu=89.5%); only the u32 tie-compare and the
// l-select remain ALU.
// Network identical to R7 (validated): bitonic sort-16 of four 8-lane groups
// in parallel, two bitonic-halving tree merges; top-16 sorted in lanes 0-7
// (2 keys/lane). Gather from L1-hot row, coalesced stores.

#define WPB 8          // warps per block
#define RPW 8          // rows per warp

// compare-exchange vs shuffled partner; keep partner iff (partner>e)==takeMax
__device__ __forceinline__ void cex2(float& h, unsigned& l, float ph, unsigned pl, bool takeMax) {
    bool g = (ph > h) || ((ph == h) && (pl > l));
    bool w = (g == takeMax);
    h = w ? ph : h;
    l = w ? pl : l;
}

template <int JH>
__device__ __forceinline__ void stage_x(float& h0, unsigned& l0, float& h1, unsigned& l1, bool takeMax) {
    float    p0h = __shfl_xor_sync(0xffffffffu, h0, JH);
    unsigned p0l = __shfl_xor_sync(0xffffffffu, l0, JH);
    float    p1h = __shfl_xor_sync(0xffffffffu, h1, JH);
    unsigned p1l = __shfl_xor_sync(0xffffffffu, l1, JH);
    cex2(h0, l0, p0h, p0l, takeMax);
    cex2(h1, l1, p1h, p1l, takeMax);
}

// element distance 1: both elements in-lane
__device__ __forceinline__ void stage_l(float& h0, unsigned& l0, float& h1, unsigned& l1, bool descR) {
    bool g = (h0 > h1) || ((h0 == h1) && (l0 > l1));   // e0 strictly greater
    bool keep = (g == descR);
    float    ha = keep ? h0 : h1;
    float    hb = keep ? h1 : h0;
    unsigned la = keep ? l0 : l1;
    unsigned lb = keep ? l1 : l0;
    h0 = ha; h1 = hb; l0 = la; l1 = lb;
}

// bitonic-halving merge step vs slot-flipped partner at lane^XM: e0 vs p1, e1 vs p0
template <int XM>
__device__ __forceinline__ void halve_x(float& h0, unsigned& l0, float& h1, unsigned& l1) {
    float    p0h = __shfl_xor_sync(0xffffffffu, h0, XM);
    unsigned p0l = __shfl_xor_sync(0xffffffffu, l0, XM);
    float    p1h = __shfl_xor_sync(0xffffffffu, h1, XM);
    unsigned p1l = __shfl_xor_sync(0xffffffffu, l1, XM);
    bool g0 = (p1h > h0) || ((p1h == h0) && (p1l > l0));
    h0 = g0 ? p1h : h0;  l0 = g0 ? p1l : l0;
    bool g1 = (p0h > h1) || ((p0h == h1) && (p0l > l1));
    h1 = g1 ? p0h : h1;  l1 = g1 ? p0l : l1;
}

__global__ void __launch_bounds__(WPB * 32)
vecnorm_topk_kernel(const float* __restrict__ x, float* __restrict__ out, int nrows)
{
    const int lane = threadIdx.x & 31;
    const int wg   = blockIdx.x * WPB + (threadIdx.x >> 5);
    const int rowBase = wg * RPW;
    if (rowBase >= nrows) return;
    const int rowsHere = min(RPW, nrows - rowBase);

    // per-lane output routing constants
    const int f2 = 32 + lane;
    const int j1 = lane / 3, c1 = lane - 3 * j1;   // out float [lane]  <- rank j1 comp c1
    const int j2 = f2 / 3,   c2 = f2 - 3 * j2;     // out float [32+l]  <- rank j2 comp c2

    // hoisted direction predicates (row-independent)
    const bool d2 = ((lane & 1) == 0);
    const bool d4 = ((lane & 2) == 0);
    const bool d8 = ((lane & 4) == 0);
    const bool x1_d4 = (d2 == d4);
    const bool x2_d8 = (((lane & 2) == 0) == d8);
    const bool x1_d8 = (d2 == d8);
    const bool x4_T  = ((lane & 4) == 0);
    const bool x2_T  = ((lane & 2) == 0);
    const bool x1_T  = d2;

    const unsigned l0init = (unsigned)(63 - 2 * lane);
    const unsigned l1init = (unsigned)(62 - 2 * lane);

    const float* xr   = x   + (size_t)rowBase * 192;
    float*       outr = out + (size_t)rowBase * 48;

#pragma unroll 1
    for (int i = 0; i < rowsHere; i++) {
        // ---- load 6 floats (vectors 2*lane, 2*lane+1), coalesced ----
        const float2* xr2 = reinterpret_cast<const float2*>(xr);
        float2 a = xr2[3 * lane + 0];
        float2 b = xr2[3 * lane + 1];
        float2 c = xr2[3 * lane + 2];
        float h0 = fmaf(a.x, a.x, fmaf(a.y, a.y, b.x * b.x));
        float h1 = fmaf(b.y, b.y, fmaf(c.x, c.x, c.y * c.y));
        unsigned l0 = l0init;
        unsigned l1 = l1init;

        // ---- bitonic sort-16 (desc) within each 8-lane group, 4 in parallel ----
        stage_l(h0, l0, h1, l1, d2);               // k=2  j=1
        stage_x<1>(h0, l0, h1, l1, x1_d4);         // k=4  j=2
        stage_l(h0, l0, h1, l1, d4);               //      j=1
        stage_x<2>(h0, l0, h1, l1, x2_d8);         // k=8  j=4
        stage_x<1>(h0, l0, h1, l1, x1_d8);         //      j=2
        stage_l(h0, l0, h1, l1, d8);               //      j=1
        stage_x<4>(h0, l0, h1, l1, x4_T);          // k=16 j=8 (final run: desc)
        stage_x<2>(h0, l0, h1, l1, x2_T);          //      j=4
        stage_x<1>(h0, l0, h1, l1, x1_T);          //      j=2
        stage_l(h0, l0, h1, l1, true);             //      j=1

        // ---- merge A: (g0,g1)->lanes0-7, (g2,g3)->lanes16-23 (parallel) ----
        halve_x<15>(h0, l0, h1, l1);               // partner elem 15-i = lane^15, slot flip
        stage_x<4>(h0, l0, h1, l1, x4_T);          // clean j=8
        stage_x<2>(h0, l0, h1, l1, x2_T);          //       j=4
        stage_x<1>(h0, l0, h1, l1, x1_T);          //       j=2
        stage_l(h0, l0, h1, l1, true);             //       j=1

        // ---- merge B: lanes0-7 vs lanes16-23 -> top-16 in lanes 0-7 ----
        halve_x<23>(h0, l0, h1, l1);               // partner lane = l ^ 23, slot flip
        stage_x<4>(h0, l0, h1, l1, x4_T);
        stage_x<2>(h0, l0, h1, l1, x2_T);
        stage_x<1>(h0, l0, h1, l1, x1_T);
        stage_l(h0, l0, h1, l1, true);

        // ---- extract indices, broadcast, gather (L1-hot), coalesced store ----
        unsigned idx0 = 63u - l0;                  // l is exactly 63-idx
        unsigned idx1 = 63u - l1;
        unsigned pk = idx0 | (idx1 << 8);          // rank 2l | rank 2l+1

        unsigned pkA = __shfl_sync(0xffffffffu, pk, j1 >> 1);
        unsigned iA  = (j1 & 1) ? ((pkA >> 8) & 0xffu) : (pkA & 0xffu);
        unsigned pkB = __shfl_sync(0xffffffffu, pk, j2 >> 1);
        unsigned iB  = (j2 & 1) ? ((pkB >> 8) & 0xffu) : (pkB & 0xffu);

        outr[lane] = xr[(int)iA * 3 + c1];
        if (lane < 16)
            outr[32 + lane] = xr[(int)iB * 3 + c2];

        xr   += 192;
        outr += 48;
    }
}

extern "C" void kernel_launch(void* const* d_in, const int* in_sizes, int n_in,
                              void* d_out, int out_size)
{
    const float* x   = (const float*)d_in[0];
    float*       out = (float*)d_out;
    int nrows = in_sizes[0] / 192;
    int rowsPerBlock = WPB * RPW;
    int grid = (nrows + rowsPerBlock - 1) / rowsPerBlock;
    vecnorm_topk_kernel<<<grid, WPB * 32>>>(x, out, nrows);
}

// round 10
// speedup vs baseline: 6.8048x; 1.5784x over previous
#include <cuda_runtime.h>

// VectorNormSelection, round 10: R7 network, split-register keys.
// Key ordering identical to R7: u64 (norm_bits << 32) | (63 - idx), EXACT
// jax.lax.top_k (value desc, index asc) semantics. The key is STORED as two
// u32 registers (hi = norm bits, lo = 63-idx):
//   - compare: reconstructed u64 (register pair, zero pack cost) ->
//     ISETP.U32 + ISETP.EX, same 2 ALU ops as R7.
//   - select: hi selected as float (__uint_as_float ternary -> FSEL, FMA
//     pipe, which sits ~95% idle at R7's alu=89.5%); lo selected with SELP.
// Everything else (wiring, lane layout, RPW, epilogue) is R7 verbatim.

#define WPB 8          // warps per block
#define RPW 4          // rows per warp

typedef unsigned long long u64;
typedef unsigned u32;

__device__ __forceinline__ u64 mkk(u32 hi, u32 lo) {
    return ((u64)hi << 32) | (u64)lo;      // reg pair; no instructions when hi/lo live
}

// select hi via float path (FSEL, fma pipe); bits preserved exactly
__device__ __forceinline__ u32 fselbits(bool p, u32 a, u32 b) {
    return __float_as_uint(p ? __uint_as_float(a) : __uint_as_float(b));
}

// compare-exchange vs shuffled partner (keep partner iff (partner>e)==takeMax)
__device__ __forceinline__ void cexg(u32& hi, u32& lo, u32 phi, u32 plo, bool takeMax) {
    bool w = ((mkk(phi, plo) > mkk(hi, lo)) == takeMax);
    hi = fselbits(w, phi, hi);
    lo = w ? plo : lo;
}

// shuffle stage, partner lane = lane ^ JH, same slot
template <int JH>
__device__ __forceinline__ void stage_x(u32& h0, u32& l0, u32& h1, u32& l1, bool takeMax) {
    u32 ph0 = __shfl_xor_sync(0xffffffffu, h0, JH);
    u32 pl0 = __shfl_xor_sync(0xffffffffu, l0, JH);
    u32 ph1 = __shfl_xor_sync(0xffffffffu, h1, JH);
    u32 pl1 = __shfl_xor_sync(0xffffffffu, l1, JH);
    cexg(h0, l0, ph0, pl0, takeMax);
    cexg(h1, l1, ph1, pl1, takeMax);
}

// element distance 1: both elements in-lane (swap), direction descR
__device__ __forceinline__ void stage_l(u32& h0, u32& l0, u32& h1, u32& l1, bool descR) {
    bool w = ((mkk(h0, l0) > mkk(h1, l1)) == descR);   // w: keep as-is
    u32 nh0 = fselbits(w, h0, h1);
    u32 nh1 = fselbits(w, h1, h0);
    u32 nl0 = w ? l0 : l1;
    u32 nl1 = w ? l1 : l0;
    h0 = nh0; h1 = nh1; l0 = nl0; l1 = nl1;
}

// bitonic-halving merge vs slot-flipped partner at lane^XM: e0 vs p1, e1 vs p0; keep max
template <int XM>
__device__ __forceinline__ void halve_x(u32& h0, u32& l0, u32& h1, u32& l1) {
    u32 ph0 = __shfl_xor_sync(0xffffffffu, h0, XM);
    u32 pl0 = __shfl_xor_sync(0xffffffffu, l0, XM);
    u32 ph1 = __shfl_xor_sync(0xffffffffu, h1, XM);
    u32 pl1 = __shfl_xor_sync(0xffffffffu, l1, XM);
    bool g0 = mkk(ph1, pl1) > mkk(h0, l0);
    h0 = fselbits(g0, ph1, h0);
    l0 = g0 ? pl1 : l0;
    bool g1 = mkk(ph0, pl0) > mkk(h1, l1);
    h1 = fselbits(g1, ph0, h1);
    l1 = g1 ? pl0 : l1;
}

__global__ void __launch_bounds__(WPB * 32)
vecnorm_topk_kernel(const float* __restrict__ x, float* __restrict__ out, int nrows)
{
    const int lane = threadIdx.x & 31;
    const int wg   = blockIdx.x * WPB + (threadIdx.x >> 5);
    const int rowBase = wg * RPW;

    // per-lane output routing constants
    const int f2 = 32 + lane;
    const int j1 = lane / 3, c1 = lane - 3 * j1;   // out float [lane]  <- rank j1 comp c1
    const int j2 = f2 / 3,   c2 = f2 - 3 * j2;     // out float [32+l]  <- rank j2 comp c2

    // hoisted direction predicates (row-independent)
    const bool d2 = ((lane & 1) == 0);
    const bool d4 = ((lane & 2) == 0);
    const bool d8 = ((lane & 4) == 0);
    const bool x1_d4 = (d2 == d4);
    const bool x2_d8 = (((lane & 2) == 0) == d8);
    const bool x1_d8 = (d2 == d8);
    const bool x4_T  = ((lane & 4) == 0);
    const bool x2_T  = ((lane & 2) == 0);
    const bool x1_T  = d2;

    const u32 l0i = (u32)(63 - 2 * lane);
    const u32 l1i = (u32)(62 - 2 * lane);

#pragma unroll 1
    for (int i = 0; i < RPW; i++) {
        int row = rowBase + i;
        if (row >= nrows) break;

        // ---- load 6 floats (vectors 2*lane, 2*lane+1), coalesced ----
        const float* xr = x + (size_t)row * 192;
        const float2* xr2 = reinterpret_cast<const float2*>(xr);
        float2 a = xr2[3 * lane + 0];
        float2 b = xr2[3 * lane + 1];
        float2 c = xr2[3 * lane + 2];
        float n0 = fmaf(a.x, a.x, fmaf(a.y, a.y, b.x * b.x));
        float n1 = fmaf(b.y, b.y, fmaf(c.x, c.x, c.y * c.y));

        // ---- split-register exact keys ----
        u32 h0 = __float_as_uint(n0), l0 = l0i;
        u32 h1 = __float_as_uint(n1), l1 = l1i;

        // ---- bitonic sort-16 (desc) within each 8-lane group, 4 in parallel ----
        stage_l(h0, l0, h1, l1, d2);               // k=2  j=1
        stage_x<1>(h0, l0, h1, l1, x1_d4);         // k=4  j=2
        stage_l(h0, l0, h1, l1, d4);               //      j=1
        stage_x<2>(h0, l0, h1, l1, x2_d8);         // k=8  j=4
        stage_x<1>(h0, l0, h1, l1, x1_d8);         //      j=2
        stage_l(h0, l0, h1, l1, d8);               //      j=1
        stage_x<4>(h0, l0, h1, l1, x4_T);          // k=16 j=8 (final run: desc)
        stage_x<2>(h0, l0, h1, l1, x2_T);          //      j=4
        stage_x<1>(h0, l0, h1, l1, x1_T);          //      j=2
        stage_l(h0, l0, h1, l1, true);             //      j=1

        // ---- merge A: (g0,g1)->lanes0-7, (g2,g3)->lanes16-23 (parallel) ----
        halve_x<15>(h0, l0, h1, l1);               // partner elem 15-i = lane^15, slot flip
        stage_x<4>(h0, l0, h1, l1, x4_T);          // clean j=8
        stage_x<2>(h0, l0, h1, l1, x2_T);          //       j=4
        stage_x<1>(h0, l0, h1, l1, x1_T);          //       j=2
        stage_l(h0, l0, h1, l1, true);             //       j=1

        // ---- merge B: lanes0-7 vs lanes16-23 -> top-16 in lanes 0-7 ----
        halve_x<23>(h0, l0, h1, l1);               // partner lane = l ^ 23, slot flip
        stage_x<4>(h0, l0, h1, l1, x4_T);
        stage_x<2>(h0, l0, h1, l1, x2_T);
        stage_x<1>(h0, l0, h1, l1, x1_T);
        stage_l(h0, l0, h1, l1, true);

        // ---- extract indices, broadcast, gather (L1-hot), coalesced store ----
        unsigned idx0 = 63u - l0;
        unsigned idx1 = 63u - l1;
        unsigned pk = idx0 | (idx1 << 8);          // rank 2l | rank 2l+1

        unsigned pkA = __shfl_sync(0xffffffffu, pk, j1 >> 1);
        unsigned iA  = (j1 & 1) ? ((pkA >> 8) & 0xffu) : (pkA & 0xffu);
        unsigned pkB = __shfl_sync(0xffffffffu, pk, j2 >> 1);
        unsigned iB  = (j2 & 1) ? ((pkB >> 8) & 0xffu) : (pkB & 0xffu);

        float* outr = out + (size_t)row * 48;
        outr[lane] = xr[(int)iA * 3 + c1];
        if (lane < 16)
            outr[32 + lane] = xr[(int)iB * 3 + c2];
    }
}

extern "C" void kernel_launch(void* const* d_in, const int* in_sizes, int n_in,
                              void* d_out, int out_size)
{
    const float* x   = (const float*)d_in[0];
    float*       out = (float*)d_out;
    int nrows = in_sizes[0] / 192;
    int rowsPerBlock = WPB * RPW;
    int grid = (nrows + rowsPerBlock - 1) / rowsPerBlock;
    vecnorm_topk_kernel<<<grid, WPB * 32>>>(x, out, nrows);
}